// round 1
// baseline (speedup 1.0000x reference)
#include <cuda_runtime.h>
#include <cuda_bf16.h>

// Problem constants
#define NS    4096      // B*T
#define SDIM  512
#define AG    16        // agents
#define ACT   20
#define MOUT  320       // AG*ACT
#define EDIM  64
#define COLS  1216      // 1024 (w1) + 64 (b1) + 64 (wf) + 64 (zv)

// GEMM tiling
#define BM 128
#define BN 64
#define BK 32
#define APAD 4
#define BPAD 2

// Scratch for hyper-network outputs: C[N, 1216] row-major
__device__ float g_C[NS * COLS];

// ---------- packed f32x2 helpers ----------
__device__ __forceinline__ unsigned long long dup2(float x) {
    unsigned long long r;
    asm("mov.b64 %0, {%1, %1};" : "=l"(r) : "f"(x));
    return r;
}
__device__ __forceinline__ unsigned long long pk2(float x, float y) {
    unsigned long long r;
    asm("mov.b64 %0, {%1, %2};" : "=l"(r) : "f"(x), "f"(y));
    return r;
}
__device__ __forceinline__ void upk2(unsigned long long p, float& x, float& y) {
    asm("mov.b64 {%0, %1}, %2;" : "=f"(x), "=f"(y) : "l"(p));
}
__device__ __forceinline__ unsigned long long ffma2(unsigned long long a,
                                                    unsigned long long b,
                                                    unsigned long long c) {
    unsigned long long d;
    asm("fma.rn.f32x2 %0, %1, %2, %3;" : "=l"(d) : "l"(a), "l"(b), "l"(c));
    return d;
}

// ============================================================================
// Kernel 1: C[N, 1216] = state @ [W_h1; W_b1; W_hf; W_v1]^T + bias
// grid (19, 32): x = 64-col block, y = 128-row block. 256 threads.
// Accumulators packed along M via fma.rn.f32x2 (2x fp32 throughput).
// ============================================================================
__global__ void __launch_bounds__(256)
gemm_hyper(const float* __restrict__ Sm,
           const float* __restrict__ W_h1, const float* __restrict__ b_h1,
           const float* __restrict__ W_b1, const float* __restrict__ b_b1,
           const float* __restrict__ W_hf, const float* __restrict__ b_hf,
           const float* __restrict__ W_v1, const float* __restrict__ b_v1)
{
    __shared__ float As[BK][BM + APAD];   // k-major, padded (store-conflict relief)
    __shared__ float Bs[BK][BN + BPAD];   // k-major

    const int cb = blockIdx.x;            // 0..18
    const int rb = blockIdx.y;            // 0..31

    const float* Wp;
    const float* bp;
    if (cb < 16)        { Wp = W_h1 + cb * 64 * SDIM; bp = b_h1 + cb * 64; }
    else if (cb == 16)  { Wp = W_b1; bp = b_b1; }
    else if (cb == 17)  { Wp = W_hf; bp = b_hf; }
    else                { Wp = W_v1; bp = b_v1; }

    const int tid = threadIdx.x;
    const int tn  = tid & 15;             // 0..15 -> n cols {2tn,2tn+1,32+2tn,33+2tn}
    const int tm  = tid >> 4;             // 0..15 -> m rows tm*8 .. tm*8+7

    unsigned long long acc[4][4];         // [m-pair][n-slot]
    #pragma unroll
    for (int i = 0; i < 4; i++)
        #pragma unroll
        for (int j = 0; j < 4; j++)
            acc[i][j] = 0ull;

    const float* Abase = Sm + (size_t)(rb * BM) * SDIM;

    for (int kt = 0; kt < SDIM; kt += BK) {
        // --- load A tile 128x32 (transpose to k-major) : 4 float4 / thread ---
        #pragma unroll
        for (int t = 0; t < 4; t++) {
            int idx = tid + t * 256;
            int row = idx >> 3;           // 0..127
            int c4  = idx & 7;            // 0..7
            float4 v = *(const float4*)(Abase + (size_t)row * SDIM + kt + c4 * 4);
            As[c4 * 4 + 0][row] = v.x;
            As[c4 * 4 + 1][row] = v.y;
            As[c4 * 4 + 2][row] = v.z;
            As[c4 * 4 + 3][row] = v.w;
        }
        // --- load B tile 64x32 (transpose to k-major) : 2 float4 / thread ---
        #pragma unroll
        for (int t = 0; t < 2; t++) {
            int idx = tid + t * 256;
            int row = idx >> 3;           // 0..63 (n)
            int c4  = idx & 7;
            float4 v = *(const float4*)(Wp + (size_t)row * SDIM + kt + c4 * 4);
            Bs[c4 * 4 + 0][row] = v.x;
            Bs[c4 * 4 + 1][row] = v.y;
            Bs[c4 * 4 + 2][row] = v.z;
            Bs[c4 * 4 + 3][row] = v.w;
        }
        __syncthreads();

        #pragma unroll
        for (int k = 0; k < BK; k++) {
            float4 a0 = *(const float4*)&As[k][tm * 8];
            float4 a1 = *(const float4*)&As[k][tm * 8 + 4];
            unsigned long long ap[4];
            ap[0] = pk2(a0.x, a0.y);
            ap[1] = pk2(a0.z, a0.w);
            ap[2] = pk2(a1.x, a1.y);
            ap[3] = pk2(a1.z, a1.w);

            float2 bA = *(const float2*)&Bs[k][2 * tn];
            float2 bB = *(const float2*)&Bs[k][32 + 2 * tn];
            unsigned long long bd[4];
            bd[0] = dup2(bA.x);
            bd[1] = dup2(bA.y);
            bd[2] = dup2(bB.x);
            bd[3] = dup2(bB.y);

            #pragma unroll
            for (int mp = 0; mp < 4; mp++)
                #pragma unroll
                for (int nv = 0; nv < 4; nv++)
                    acc[mp][nv] = ffma2(ap[mp], bd[nv], acc[mp][nv]);
        }
        __syncthreads();
    }

    // --- epilogue: add bias, write C ---
    const float bias0 = bp[2 * tn];
    const float bias1 = bp[2 * tn + 1];
    const float bias2 = bp[32 + 2 * tn];
    const float bias3 = bp[33 + 2 * tn];

    #pragma unroll
    for (int mp = 0; mp < 4; mp++) {
        float lo0, hi0, lo1, hi1, lo2, hi2, lo3, hi3;
        upk2(acc[mp][0], lo0, hi0);
        upk2(acc[mp][1], lo1, hi1);
        upk2(acc[mp][2], lo2, hi2);
        upk2(acc[mp][3], lo3, hi3);

        int m0 = rb * BM + tm * 8 + mp * 2;
        float* r0 = g_C + (size_t)m0 * COLS + cb * 64;
        float* r1 = r0 + COLS;

        float2 s;
        s.x = lo0 + bias0; s.y = lo1 + bias1; *(float2*)(r0 + 2 * tn)      = s;
        s.x = lo2 + bias2; s.y = lo3 + bias3; *(float2*)(r0 + 32 + 2 * tn) = s;
        s.x = hi0 + bias0; s.y = hi1 + bias1; *(float2*)(r1 + 2 * tn)      = s;
        s.x = hi2 + bias2; s.y = hi3 + bias3; *(float2*)(r1 + 32 + 2 * tn) = s;
    }
}

// ============================================================================
// Kernel 2: mixer. One warp per sample n.
//   qt[i] = q_agents[n,i,actions[n,i]]
//   base[e] = sum_j qt[j]*w1[n,j,e];  u[e] = base[e] + b1[e]
//   y[n, i*20+act] = sum_e elu(u[e] + (q_agents[n,i,act]-qt[i])*w1[n,i,e])*wf[e] + v
//   v = sum_e relu(zv[e])*W_v2[e] + b_v2
// Lane layout: lane = eg*8 + ms; eg in 0..3 owns 16 e-values; ms in 0..7 is an
// action slot. Butterfly shfl_xor(8,16) reduces over e-groups.
// ============================================================================
__global__ void __launch_bounds__(256)
mixer(const float* __restrict__ q_agents,
      const int*   __restrict__ actions,
      const float* __restrict__ W_v2,
      const float* __restrict__ b_v2,
      float*       __restrict__ out)
{
    const int warp = (blockIdx.x * blockDim.x + threadIdx.x) >> 5;
    if (warp >= NS) return;
    const int n    = warp;
    const int lane = threadIdx.x & 31;
    const int eg   = lane >> 3;          // 0..3
    const int ms   = lane & 7;           // 0..7

    const float* Crow = g_C + (size_t)n * COLS;
    const unsigned FULL = 0xffffffffu;

    // qt for lanes 0..15
    float qt_own = 0.f;
    if (lane < AG) {
        int a = actions[n * AG + lane];
        qt_own = q_agents[(size_t)(n * AG + lane) * ACT + a];
    }

    // v (zv already includes b_v1 via GEMM epilogue)
    float zv0 = Crow[1152 + lane];
    float zv1 = Crow[1152 + 32 + lane];
    float vp  = fmaxf(zv0, 0.f) * W_v2[lane] + fmaxf(zv1, 0.f) * W_v2[lane + 32];
    #pragma unroll
    for (int off = 16; off >= 1; off >>= 1)
        vp += __shfl_xor_sync(FULL, vp, off);
    const float v = vp + b_v2[0];

    const int e0 = eg * 16;

    // u[e] = b1[e] + sum_j qt[j]*w1[j,e]
    float u[16];
    {
        const float4* p = (const float4*)(Crow + 1024 + e0);
        #pragma unroll
        for (int j = 0; j < 4; j++) {
            float4 t = p[j];
            u[4 * j + 0] = t.x; u[4 * j + 1] = t.y;
            u[4 * j + 2] = t.z; u[4 * j + 3] = t.w;
        }
    }
    #pragma unroll 1
    for (int i = 0; i < AG; i++) {
        float qti = __shfl_sync(FULL, qt_own, i);
        const float4* p = (const float4*)(Crow + i * EDIM + e0);
        #pragma unroll
        for (int j = 0; j < 4; j++) {
            float4 t = p[j];
            u[4 * j + 0] = fmaf(qti, t.x, u[4 * j + 0]);
            u[4 * j + 1] = fmaf(qti, t.y, u[4 * j + 1]);
            u[4 * j + 2] = fmaf(qti, t.z, u[4 * j + 2]);
            u[4 * j + 3] = fmaf(qti, t.w, u[4 * j + 3]);
        }
    }

    // wf and its lane-partial sum (folds the elu "-1" out of the inner loop)
    float wf[16];
    float swf = 0.f;
    {
        const float4* p = (const float4*)(Crow + 1088 + e0);
        #pragma unroll
        for (int j = 0; j < 4; j++) {
            float4 t = p[j];
            wf[4 * j + 0] = t.x; wf[4 * j + 1] = t.y;
            wf[4 * j + 2] = t.z; wf[4 * j + 3] = t.w;
        }
        #pragma unroll
        for (int e = 0; e < 16; e++) swf += wf[e];
    }

    // main loop over agents / action blocks
    #pragma unroll 1
    for (int i = 0; i < AG; i++) {
        float w[16];
        const float4* p = (const float4*)(Crow + i * EDIM + e0);
        #pragma unroll
        for (int j = 0; j < 4; j++) {
            float4 t = p[j];
            w[4 * j + 0] = t.x; w[4 * j + 1] = t.y;
            w[4 * j + 2] = t.z; w[4 * j + 3] = t.w;
        }
        float qti = __shfl_sync(FULL, qt_own, i);
        const float* qrow = q_agents + (size_t)(n * AG + i) * ACT;

        #pragma unroll
        for (int blk = 0; blk < 3; blk++) {
            int act  = blk * 8 + ms;
            int actc = act < (ACT - 1) ? act : (ACT - 1);
            float delta = qrow[actc] - qti;

            float accv = 0.f;
            #pragma unroll
            for (int e = 0; e < 16; e++) {
                float x = fmaf(delta, w[e], u[e]);
                // elu(x)+1 = max(x,0) + exp(min(x,0)); "-1" folded via swf
                float t = fmaxf(x, 0.f) + __expf(fminf(x, 0.f));
                accv = fmaf(t, wf[e], accv);
            }
            accv -= swf;
            accv += __shfl_xor_sync(FULL, accv, 8);
            accv += __shfl_xor_sync(FULL, accv, 16);
            if (eg == 0 && act < ACT)
                out[(size_t)n * MOUT + i * ACT + act] = accv + v;
        }
    }
}

// ============================================================================
extern "C" void kernel_launch(void* const* d_in, const int* in_sizes, int n_in,
                              void* d_out, int out_size) {
    const float* q_agents = (const float*)d_in[0];
    const int*   actions  = (const int*)d_in[1];
    const float* state    = (const float*)d_in[2];
    const float* W_h1 = (const float*)d_in[3];
    const float* b_h1 = (const float*)d_in[4];
    const float* W_b1 = (const float*)d_in[5];
    const float* b_b1 = (const float*)d_in[6];
    const float* W_hf = (const float*)d_in[7];
    const float* b_hf = (const float*)d_in[8];
    const float* W_v1 = (const float*)d_in[9];
    const float* b_v1 = (const float*)d_in[10];
    const float* W_v2 = (const float*)d_in[11];
    const float* b_v2 = (const float*)d_in[12];
    float* out = (float*)d_out;

    dim3 g1(19, 32);
    gemm_hyper<<<g1, 256>>>(state, W_h1, b_h1, W_b1, b_b1, W_hf, b_hf, W_v1, b_v1);
    mixer<<<(NS * 32 + 255) / 256, 256>>>(q_agents, actions, W_v2, b_v2, out);
    (void)in_sizes; (void)n_in; (void)out_size;
}

// round 3
// speedup vs baseline: 1.4204x; 1.4204x over previous
#include <cuda_runtime.h>
#include <cuda_bf16.h>
#include <cstdint>

// ---------------- problem constants ----------------
#define NS    4096      // B*T
#define SDIM  512
#define AG    16
#define ACT   20
#define MOUT  320
#define EDIM  64
#define COLS  1216      // 1024 w1 + 64 b1 + 64 wf + 64 zv
#define COLSP 1280      // padded to 10*128

#define LOG2E 1.4426950408889634f
#define LN2   0.6931471805599453f

// ---------------- device scratch ----------------
__device__ float          g_C[NS * COLS];
__device__ __nv_bfloat16  g_A0[NS * SDIM];
__device__ __nv_bfloat16  g_A1[NS * SDIM];
__device__ __nv_bfloat16  g_B0[COLSP * SDIM];
__device__ __nv_bfloat16  g_B1[COLSP * SDIM];
__device__ float          g_bias[COLSP];

// ---------------- PTX helpers (sm_100-safe: no tcgen05) ----------------
__device__ __forceinline__ uint32_t smem_u32(const void* p) {
    uint32_t a;
    asm("{ .reg .u64 t; cvta.to.shared.u64 t, %1; cvt.u32.u64 %0, t; }" : "=r"(a) : "l"(p));
    return a;
}
__device__ __forceinline__ void cp16(uint32_t dst, const void* src) {
    asm volatile("cp.async.cg.shared.global [%0], [%1], 16;" :: "r"(dst), "l"(src));
}
#define CP_COMMIT() asm volatile("cp.async.commit_group;" ::: "memory")
#define CP_WAIT2()  asm volatile("cp.async.wait_group 2;" ::: "memory")

__device__ __forceinline__ void ldm_x4(uint32_t* r, uint32_t addr) {
    asm volatile("ldmatrix.sync.aligned.m8n8.x4.shared.b16 {%0,%1,%2,%3}, [%4];"
        : "=r"(r[0]), "=r"(r[1]), "=r"(r[2]), "=r"(r[3]) : "r"(addr));
}
__device__ __forceinline__ void mma_bf16(float* c, const uint32_t* a, uint32_t b0, uint32_t b1) {
    asm volatile(
        "mma.sync.aligned.m16n8k16.row.col.f32.bf16.bf16.f32 "
        "{%0,%1,%2,%3}, {%4,%5,%6,%7}, {%8,%9}, {%0,%1,%2,%3};"
        : "+f"(c[0]), "+f"(c[1]), "+f"(c[2]), "+f"(c[3])
        : "r"(a[0]), "r"(a[1]), "r"(a[2]), "r"(a[3]), "r"(b0), "r"(b1));
}
__device__ __forceinline__ float ex2f(float x) {
    float y;
    asm("ex2.approx.ftz.f32 %0, %1;" : "=f"(y) : "f"(x));
    return y;
}

// ============================================================================
// Kernel 0: split fp32 -> (bf16 hi, bf16 residual); concat weights/bias.
// ============================================================================
__device__ __forceinline__ uint32_t pack2bf(float a, float b) {
    __nv_bfloat162 t(__float2bfloat16_rn(a), __float2bfloat16_rn(b));
    return *(uint32_t*)&t;
}

__global__ void __launch_bounds__(256)
convert_split(const float* __restrict__ state,
              const float* __restrict__ W_h1, const float* __restrict__ b_h1,
              const float* __restrict__ W_b1, const float* __restrict__ b_b1,
              const float* __restrict__ W_hf, const float* __restrict__ b_hf,
              const float* __restrict__ W_v1, const float* __restrict__ b_v1)
{
    const int AQ = NS * SDIM / 4;        // 524288
    const int BQ = COLSP * SDIM / 4;     // 163840
    int idx = blockIdx.x * blockDim.x + threadIdx.x;

    if (idx < AQ) {
        float4 v = ((const float4*)state)[idx];
        float h0 = __bfloat162float(__float2bfloat16_rn(v.x));
        float h1 = __bfloat162float(__float2bfloat16_rn(v.y));
        float h2 = __bfloat162float(__float2bfloat16_rn(v.z));
        float h3 = __bfloat162float(__float2bfloat16_rn(v.w));
        uint2 p0, p1;
        p0.x = pack2bf(v.x, v.y);  p0.y = pack2bf(v.z, v.w);
        p1.x = pack2bf(v.x - h0, v.y - h1);
        p1.y = pack2bf(v.z - h2, v.w - h3);
        ((uint2*)g_A0)[idx] = p0;
        ((uint2*)g_A1)[idx] = p1;
    } else if (idx < AQ + BQ) {
        int q = idx - AQ;
        int row = q >> 7;                // SDIM/4 = 128 quads per row
        int cq  = q & 127;
        float4 v = make_float4(0.f, 0.f, 0.f, 0.f);
        if (row < 1024)      v = ((const float4*)(W_h1 + (size_t)row * SDIM))[cq];
        else if (row < 1088) v = ((const float4*)(W_b1 + (size_t)(row - 1024) * SDIM))[cq];
        else if (row < 1152) v = ((const float4*)(W_hf + (size_t)(row - 1088) * SDIM))[cq];
        else if (row < 1216) v = ((const float4*)(W_v1 + (size_t)(row - 1152) * SDIM))[cq];
        float h0 = __bfloat162float(__float2bfloat16_rn(v.x));
        float h1 = __bfloat162float(__float2bfloat16_rn(v.y));
        float h2 = __bfloat162float(__float2bfloat16_rn(v.z));
        float h3 = __bfloat162float(__float2bfloat16_rn(v.w));
        uint2 p0, p1;
        p0.x = pack2bf(v.x, v.y);  p0.y = pack2bf(v.z, v.w);
        p1.x = pack2bf(v.x - h0, v.y - h1);
        p1.y = pack2bf(v.z - h2, v.w - h3);
        ((uint2*)g_B0)[q] = p0;
        ((uint2*)g_B1)[q] = p1;
    } else if (idx < AQ + BQ + COLSP) {
        int c = idx - AQ - BQ;
        float b = 0.f;
        if (c < 1024)      b = b_h1[c];
        else if (c < 1088) b = b_b1[c - 1024];
        else if (c < 1152) b = b_hf[c - 1088];
        else if (c < 1216) b = b_v1[c - 1152];
        g_bias[c] = b;
    }
}

// ============================================================================
// Kernel 1: HMMA bf16 GEMM, split: C = A0*B0 + A0*B1 + A1*B0 + bias
// Tile 128(M) x 128(N) x 32(K). 256 threads = 8 warps (2m x 4n), warp 64x32.
// 3-stage cp.async pipeline. Rows padded to 40 bf16 (80B) -> conflict-free
// ldmatrix (banks {0,20,8,28,16,4,24,12}).
// ============================================================================
#define ROWB   80                       // padded row bytes (32 bf16 + 8 pad)
#define MATB   (128 * ROWB)             // 10240 B per matrix tile
#define STAGEB (4 * MATB)               // 40960 B per stage
#define NSTAGE 3
#define GEMM_SMEM (NSTAGE * STAGEB)     // 122880 B

__device__ __forceinline__ void load_stage(uint32_t sb, int tid, int rowA, int rowB, int kt) {
    // kt in bf16 units (k offset). Each thread: 2 chunks per matrix.
    #pragma unroll
    for (int t = 0; t < 2; t++) {
        int id = tid + t * 256;          // 0..511
        int r  = id >> 2;                // 0..127
        int c  = id & 3;                 // 16B chunk in row
        uint32_t soff = (uint32_t)(r * ROWB + c * 16);
        size_t gA = ((size_t)(rowA + r) * SDIM + kt) * 2 + c * 16;
        size_t gB = ((size_t)(rowB + r) * SDIM + kt) * 2 + c * 16;
        cp16(sb + 0 * MATB + soff, (const char*)g_A0 + gA);
        cp16(sb + 1 * MATB + soff, (const char*)g_A1 + gA);
        cp16(sb + 2 * MATB + soff, (const char*)g_B0 + gB);
        cp16(sb + 3 * MATB + soff, (const char*)g_B1 + gB);
    }
}

__global__ void __launch_bounds__(256, 1)
gemm_tc()
{
    extern __shared__ char smem[];
    const uint32_t sbase = smem_u32(smem);
    const int tid  = threadIdx.x;
    const int wid  = tid >> 5;
    const int lane = tid & 31;
    const int cb   = blockIdx.x;   // 0..9
    const int rb   = blockIdx.y;   // 0..31

    const int warp_m = wid >> 2;           // 0..1 -> m offset *64
    const int warp_n = wid & 3;            // 0..3 -> n offset *32
    const int rowA = rb * 128;
    const int rowB = cb * 128;

    float c[4][4][4];
    #pragma unroll
    for (int i = 0; i < 4; i++)
        #pragma unroll
        for (int j = 0; j < 4; j++)
            #pragma unroll
            for (int q = 0; q < 4; q++)
                c[i][j][q] = 0.f;

    // prologue: stages 0,1
    load_stage(sbase + 0 * STAGEB, tid, rowA, rowB, 0);
    CP_COMMIT();
    load_stage(sbase + 1 * STAGEB, tid, rowA, rowB, 32);
    CP_COMMIT();

    // ldmatrix base offsets for this thread (row = lane%16, col byte = (lane/16)*16)
    const uint32_t lrow = (uint32_t)(lane & 15) * ROWB;
    const uint32_t lcol = (uint32_t)(lane >> 4) * 16;   // 8 bf16

    const int NK = SDIM / 32;   // 16
    for (int kt = 0; kt < NK; kt++) {
        // issue stage kt+2 (or empty group to keep wait_group accounting fixed)
        if (kt + 2 < NK)
            load_stage(sbase + ((kt + 2) % NSTAGE) * STAGEB, tid, rowA, rowB, (kt + 2) * 32);
        CP_COMMIT();
        CP_WAIT2();
        __syncthreads();

        const uint32_t st = sbase + (kt % NSTAGE) * STAGEB;
        const uint32_t aAddr = st + lrow + lcol;               // + mt*16*ROWB + kk*32
        const uint32_t bAddr = st + 2 * MATB + (uint32_t)(warp_n * 32) * ROWB + lrow + lcol;

        #pragma unroll
        for (int kk = 0; kk < 2; kk++) {
            uint32_t a0[4][4], a1[4][4];
            #pragma unroll
            for (int mt = 0; mt < 4; mt++) {
                uint32_t ra = aAddr + (uint32_t)((warp_m * 64 + mt * 16) * ROWB + kk * 32);
                ldm_x4(a0[mt], ra);
                ldm_x4(a1[mt], ra + MATB);
            }
            uint32_t b0[2][4], b1[2][4];
            #pragma unroll
            for (int nt2 = 0; nt2 < 2; nt2++) {
                uint32_t rbad = bAddr + (uint32_t)(nt2 * 16 * ROWB + kk * 32);
                ldm_x4(b0[nt2], rbad);
                ldm_x4(b1[nt2], rbad + MATB);
            }
            #pragma unroll
            for (int mt = 0; mt < 4; mt++) {
                #pragma unroll
                for (int nt = 0; nt < 4; nt++) {
                    int h = nt >> 1, o = nt & 1;   // b frag = {r[o], r[o+2]} of x4 load
                    mma_bf16(c[mt][nt], a0[mt], b0[h][o], b0[h][o + 2]);
                    mma_bf16(c[mt][nt], a0[mt], b1[h][o], b1[h][o + 2]);
                    mma_bf16(c[mt][nt], a1[mt], b0[h][o], b0[h][o + 2]);
                }
            }
        }
        __syncthreads();
    }

    // epilogue: add bias, write to g_C (skip padded cols >= 1216)
    const int rbase = rb * 128 + warp_m * 64 + (lane >> 2);
    const int cbase = cb * 128 + warp_n * 32 + (lane & 3) * 2;
    #pragma unroll
    for (int nt = 0; nt < 4; nt++) {
        int col = cbase + nt * 8;
        if (col >= COLS) continue;
        float2 bias = *(const float2*)(g_bias + col);
        #pragma unroll
        for (int mt = 0; mt < 4; mt++) {
            int r0 = rbase + mt * 16;
            float2 v0, v1;
            v0.x = c[mt][nt][0] + bias.x; v0.y = c[mt][nt][1] + bias.y;
            v1.x = c[mt][nt][2] + bias.x; v1.y = c[mt][nt][3] + bias.y;
            *(float2*)(g_C + (size_t)r0 * COLS + col)       = v0;
            *(float2*)(g_C + (size_t)(r0 + 8) * COLS + col) = v1;
        }
    }
}

// ============================================================================
// Kernel 2: mixer. TWO warps per sample (agents split 8/8), log2-domain elu.
// ============================================================================
__global__ void __launch_bounds__(256)
mixer(const float* __restrict__ q_agents,
      const int*   __restrict__ actions,
      const float* __restrict__ W_v2,
      const float* __restrict__ b_v2,
      float*       __restrict__ out)
{
    const int gw = (blockIdx.x * blockDim.x + threadIdx.x) >> 5;
    if (gw >= NS * 2) return;
    const int n    = gw >> 1;
    const int half = gw & 1;            // agents [8h, 8h+8)
    const int lane = threadIdx.x & 31;
    const int eg   = lane >> 3;         // 0..3 -> 16 e-values each
    const int ms   = lane & 7;          // action slot
    const int e0   = eg * 16;
    const unsigned FULL = 0xffffffffu;

    const float* Crow = g_C + (size_t)n * COLS;

    float qt_own = 0.f;
    if (lane < AG) {
        int a = actions[n * AG + lane];
        qt_own = q_agents[(size_t)(n * AG + lane) * ACT + a];
    }

    // v = relu(zv) @ W_v2 + b_v2
    float zv0 = Crow[1152 + lane];
    float zv1 = Crow[1184 + lane];
    float vp  = fmaxf(zv0, 0.f) * W_v2[lane] + fmaxf(zv1, 0.f) * W_v2[lane + 32];
    #pragma unroll
    for (int off = 16; off >= 1; off >>= 1)
        vp += __shfl_xor_sync(FULL, vp, off);
    const float v = vp + b_v2[0];

    // u2[e] = LOG2E * (b1[e] + sum_j qt[j]*w1[j,e])
    float u2[16];
    {
        const float4* p = (const float4*)(Crow + 1024 + e0);
        #pragma unroll
        for (int j = 0; j < 4; j++) {
            float4 t = p[j];
            u2[4 * j + 0] = t.x; u2[4 * j + 1] = t.y;
            u2[4 * j + 2] = t.z; u2[4 * j + 3] = t.w;
        }
    }
    #pragma unroll 1
    for (int i = 0; i < AG; i++) {
        float qti = __shfl_sync(FULL, qt_own, i);
        const float4* p = (const float4*)(Crow + i * EDIM + e0);
        #pragma unroll
        for (int j = 0; j < 4; j++) {
            float4 t = p[j];
            u2[4 * j + 0] = fmaf(qti, t.x, u2[4 * j + 0]);
            u2[4 * j + 1] = fmaf(qti, t.y, u2[4 * j + 1]);
            u2[4 * j + 2] = fmaf(qti, t.z, u2[4 * j + 2]);
            u2[4 * j + 3] = fmaf(qti, t.w, u2[4 * j + 3]);
        }
    }
    #pragma unroll
    for (int e = 0; e < 16; e++) u2[e] *= LOG2E;

    // wf + lane-partial sum (folds the elu "-1")
    float wf[16], swf = 0.f;
    {
        const float4* p = (const float4*)(Crow + 1088 + e0);
        #pragma unroll
        for (int j = 0; j < 4; j++) {
            float4 t = p[j];
            wf[4 * j + 0] = t.x; wf[4 * j + 1] = t.y;
            wf[4 * j + 2] = t.z; wf[4 * j + 3] = t.w;
        }
        #pragma unroll
        for (int e = 0; e < 16; e++) swf += wf[e];
    }

    const int i0 = half * 8;
    #pragma unroll 1
    for (int i = i0; i < i0 + 8; i++) {
        float w[16];
        const float4* p = (const float4*)(Crow + i * EDIM + e0);
        #pragma unroll
        for (int j = 0; j < 4; j++) {
            float4 t = p[j];
            w[4 * j + 0] = t.x; w[4 * j + 1] = t.y;
            w[4 * j + 2] = t.z; w[4 * j + 3] = t.w;
        }
        float qti = __shfl_sync(FULL, qt_own, i);
        const float* qrow = q_agents + (size_t)(n * AG + i) * ACT;

        #pragma unroll
        for (int blk = 0; blk < 3; blk++) {
            int act  = blk * 8 + ms;
            int actc = act < (ACT - 1) ? act : (ACT - 1);
            float deltaL = (qrow[actc] - qti) * LOG2E;

            float acc1 = 0.f, acc2 = 0.f;
            #pragma unroll
            for (int e = 0; e < 16; e++) {
                float x2 = fmaf(deltaL, w[e], u2[e]);
                acc1 = fmaf(fmaxf(x2, 0.f), wf[e], acc1);
                acc2 = fmaf(ex2f(fminf(x2, 0.f)), wf[e], acc2);
            }
            float accv = fmaf(acc1, LN2, acc2) - swf;
            accv += __shfl_xor_sync(FULL, accv, 8);
            accv += __shfl_xor_sync(FULL, accv, 16);
            if (eg == 0 && act < ACT)
                out[(size_t)n * MOUT + i * ACT + act] = accv + v;
        }
    }
}

// ============================================================================
extern "C" void kernel_launch(void* const* d_in, const int* in_sizes, int n_in,
                              void* d_out, int out_size) {
    const float* q_agents = (const float*)d_in[0];
    const int*   actions  = (const int*)d_in[1];
    const float* state    = (const float*)d_in[2];
    const float* W_h1 = (const float*)d_in[3];
    const float* b_h1 = (const float*)d_in[4];
    const float* W_b1 = (const float*)d_in[5];
    const float* b_b1 = (const float*)d_in[6];
    const float* W_hf = (const float*)d_in[7];
    const float* b_hf = (const float*)d_in[8];
    const float* W_v1 = (const float*)d_in[9];
    const float* b_v1 = (const float*)d_in[10];
    const float* W_v2 = (const float*)d_in[11];
    const float* b_v2 = (const float*)d_in[12];
    float* out = (float*)d_out;

    cudaFuncSetAttribute(gemm_tc, cudaFuncAttributeMaxDynamicSharedMemorySize, GEMM_SMEM);

    int conv_threads = NS * SDIM / 4 + COLSP * SDIM / 4 + COLSP;
    convert_split<<<(conv_threads + 255) / 256, 256>>>(
        state, W_h1, b_h1, W_b1, b_b1, W_hf, b_hf, W_v1, b_v1);

    dim3 g1(10, 32);
    gemm_tc<<<g1, 256, GEMM_SMEM>>>();

    mixer<<<(NS * 2 * 32 + 255) / 256, 256>>>(q_agents, actions, W_v2, b_v2, out);
    (void)in_sizes; (void)n_in; (void)out_size;
}

// round 4
// speedup vs baseline: 1.8784x; 1.3225x over previous
#include <cuda_runtime.h>
#include <cuda_bf16.h>
#include <cuda_fp16.h>
#include <cstdint>

// ---------------- problem constants ----------------
#define NS    4096      // B*T
#define SDIM  512
#define AG    16
#define ACT   20
#define MOUT  320
#define EDIM  64
#define COLS  1216      // 1024 w1 + 64 b1 + 64 wf + 64 zv
#define COLSP 1280      // padded to 10*128

#define LOG2E 1.4426950408889634f
#define LN2   0.6931471805599453f

// ---------------- device scratch ----------------
__device__ float   g_C[NS * COLS];
__device__ __half  g_A0[NS * SDIM];          // fp16(state)
__device__ __half  g_B0[COLSP * SDIM];       // fp16(W)
__device__ __half  g_B1[COLSP * SDIM];       // fp16(W - fp16(W))
__device__ float   g_bias[COLSP];

// ---------------- PTX helpers (sm_100-safe) ----------------
__device__ __forceinline__ uint32_t smem_u32(const void* p) {
    uint32_t a;
    asm("{ .reg .u64 t; cvta.to.shared.u64 t, %1; cvt.u32.u64 %0, t; }" : "=r"(a) : "l"(p));
    return a;
}
__device__ __forceinline__ void cp16(uint32_t dst, const void* src) {
    asm volatile("cp.async.cg.shared.global [%0], [%1], 16;" :: "r"(dst), "l"(src));
}
#define CP_COMMIT() asm volatile("cp.async.commit_group;" ::: "memory")
#define CP_WAIT2()  asm volatile("cp.async.wait_group 2;" ::: "memory")

__device__ __forceinline__ void ldm_x4(uint32_t* r, uint32_t addr) {
    asm volatile("ldmatrix.sync.aligned.m8n8.x4.shared.b16 {%0,%1,%2,%3}, [%4];"
        : "=r"(r[0]), "=r"(r[1]), "=r"(r[2]), "=r"(r[3]) : "r"(addr));
}
__device__ __forceinline__ void mma_f16(float* c, const uint32_t* a, uint32_t b0, uint32_t b1) {
    asm volatile(
        "mma.sync.aligned.m16n8k16.row.col.f32.f16.f16.f32 "
        "{%0,%1,%2,%3}, {%4,%5,%6,%7}, {%8,%9}, {%0,%1,%2,%3};"
        : "+f"(c[0]), "+f"(c[1]), "+f"(c[2]), "+f"(c[3])
        : "r"(a[0]), "r"(a[1]), "r"(a[2]), "r"(a[3]), "r"(b0), "r"(b1));
}
__device__ __forceinline__ float ex2f(float x) {
    float y;
    asm("ex2.approx.ftz.f32 %0, %1;" : "=f"(y) : "f"(x));
    return y;
}

// ============================================================================
// Kernel 0: A -> fp16; W -> fp16 hi + fp16 residual; concat bias.
// ============================================================================
__device__ __forceinline__ uint32_t pack2h(float a, float b) {
    __half2 t(__float2half_rn(a), __float2half_rn(b));
    return *(uint32_t*)&t;
}

__global__ void __launch_bounds__(256)
convert_split(const float* __restrict__ state,
              const float* __restrict__ W_h1, const float* __restrict__ b_h1,
              const float* __restrict__ W_b1, const float* __restrict__ b_b1,
              const float* __restrict__ W_hf, const float* __restrict__ b_hf,
              const float* __restrict__ W_v1, const float* __restrict__ b_v1)
{
    const int AQ = NS * SDIM / 4;        // 524288
    const int BQ = COLSP * SDIM / 4;     // 163840
    int idx = blockIdx.x * blockDim.x + threadIdx.x;

    if (idx < AQ) {
        float4 v = ((const float4*)state)[idx];
        uint2 p0;
        p0.x = pack2h(v.x, v.y);  p0.y = pack2h(v.z, v.w);
        ((uint2*)g_A0)[idx] = p0;
    } else if (idx < AQ + BQ) {
        int q = idx - AQ;
        int row = q >> 7;                // SDIM/4 = 128 quads per row
        int cq  = q & 127;
        float4 v = make_float4(0.f, 0.f, 0.f, 0.f);
        if (row < 1024)      v = ((const float4*)(W_h1 + (size_t)row * SDIM))[cq];
        else if (row < 1088) v = ((const float4*)(W_b1 + (size_t)(row - 1024) * SDIM))[cq];
        else if (row < 1152) v = ((const float4*)(W_hf + (size_t)(row - 1088) * SDIM))[cq];
        else if (row < 1216) v = ((const float4*)(W_v1 + (size_t)(row - 1152) * SDIM))[cq];
        float h0 = __half2float(__float2half_rn(v.x));
        float h1 = __half2float(__float2half_rn(v.y));
        float h2 = __half2float(__float2half_rn(v.z));
        float h3 = __half2float(__float2half_rn(v.w));
        uint2 p0, p1;
        p0.x = pack2h(v.x, v.y);  p0.y = pack2h(v.z, v.w);
        p1.x = pack2h(v.x - h0, v.y - h1);
        p1.y = pack2h(v.z - h2, v.w - h3);
        ((uint2*)g_B0)[q] = p0;
        ((uint2*)g_B1)[q] = p1;
    } else if (idx < AQ + BQ + COLSP) {
        int c = idx - AQ - BQ;
        float b = 0.f;
        if (c < 1024)      b = b_h1[c];
        else if (c < 1088) b = b_b1[c - 1024];
        else if (c < 1152) b = b_hf[c - 1088];
        else if (c < 1216) b = b_v1[c - 1152];
        g_bias[c] = b;
    }
}

// ============================================================================
// Kernel 1: HMMA fp16 GEMM, 2-term: C = A0*B0 + A0*B1 + bias
// Tile 128(M) x 128(N) x 32(K). 256 threads = 8 warps (2m x 4n), warp 64x32.
// 3-stage cp.async pipeline, 2 CTAs/SM. 80B-padded rows -> conflict-free ldmatrix.
// ============================================================================
#define ROWB   80
#define MATB   (128 * ROWB)             // 10240 B
#define STAGEB (3 * MATB)               // 30720 B (A0,B0,B1)
#define NSTAGE 3
#define GEMM_SMEM (NSTAGE * STAGEB)     // 92160 B

__device__ __forceinline__ void load_stage(uint32_t sb, int tid, int rowA, int rowB, int kt) {
    #pragma unroll
    for (int t = 0; t < 2; t++) {
        int id = tid + t * 256;          // 0..511
        int r  = id >> 2;                // 0..127
        int c  = id & 3;
        uint32_t soff = (uint32_t)(r * ROWB + c * 16);
        size_t gA = ((size_t)(rowA + r) * SDIM + kt) * 2 + c * 16;
        size_t gB = ((size_t)(rowB + r) * SDIM + kt) * 2 + c * 16;
        cp16(sb + 0 * MATB + soff, (const char*)g_A0 + gA);
        cp16(sb + 1 * MATB + soff, (const char*)g_B0 + gB);
        cp16(sb + 2 * MATB + soff, (const char*)g_B1 + gB);
    }
}

__global__ void __launch_bounds__(256, 2)
gemm_tc()
{
    extern __shared__ char smem[];
    const uint32_t sbase = smem_u32(smem);
    const int tid  = threadIdx.x;
    const int wid  = tid >> 5;
    const int lane = tid & 31;
    const int cb   = blockIdx.x;   // 0..9
    const int rb   = blockIdx.y;   // 0..31

    const int warp_m = wid >> 2;           // 0..1 -> m *64
    const int warp_n = wid & 3;            // 0..3 -> n *32
    const int rowA = rb * 128;
    const int rowB = cb * 128;

    float c[4][4][4];
    #pragma unroll
    for (int i = 0; i < 4; i++)
        #pragma unroll
        for (int j = 0; j < 4; j++)
            #pragma unroll
            for (int q = 0; q < 4; q++)
                c[i][j][q] = 0.f;

    load_stage(sbase + 0 * STAGEB, tid, rowA, rowB, 0);
    CP_COMMIT();
    load_stage(sbase + 1 * STAGEB, tid, rowA, rowB, 32);
    CP_COMMIT();

    const uint32_t lrow = (uint32_t)(lane & 15) * ROWB;
    const uint32_t lcol = (uint32_t)(lane >> 4) * 16;

    const int NK = SDIM / 32;   // 16
    for (int kt = 0; kt < NK; kt++) {
        if (kt + 2 < NK)
            load_stage(sbase + ((kt + 2) % NSTAGE) * STAGEB, tid, rowA, rowB, (kt + 2) * 32);
        CP_COMMIT();
        CP_WAIT2();
        __syncthreads();

        const uint32_t st = sbase + (kt % NSTAGE) * STAGEB;
        const uint32_t aAddr = st + lrow + lcol;
        const uint32_t bAddr = st + 1 * MATB + (uint32_t)(warp_n * 32) * ROWB + lrow + lcol;

        #pragma unroll
        for (int kk = 0; kk < 2; kk++) {
            uint32_t a[4][4];
            #pragma unroll
            for (int mt = 0; mt < 4; mt++) {
                uint32_t ra = aAddr + (uint32_t)((warp_m * 64 + mt * 16) * ROWB + kk * 32);
                ldm_x4(a[mt], ra);
            }
            uint32_t b0[2][4], b1[2][4];
            #pragma unroll
            for (int nt2 = 0; nt2 < 2; nt2++) {
                uint32_t rbad = bAddr + (uint32_t)(nt2 * 16 * ROWB + kk * 32);
                ldm_x4(b0[nt2], rbad);
                ldm_x4(b1[nt2], rbad + MATB);
            }
            #pragma unroll
            for (int mt = 0; mt < 4; mt++) {
                #pragma unroll
                for (int nt = 0; nt < 4; nt++) {
                    int h = nt >> 1, o = nt & 1;
                    mma_f16(c[mt][nt], a[mt], b0[h][o], b0[h][o + 2]);
                    mma_f16(c[mt][nt], a[mt], b1[h][o], b1[h][o + 2]);
                }
            }
        }
        __syncthreads();
    }

    // epilogue
    const int rbase = rb * 128 + warp_m * 64 + (lane >> 2);
    const int cbase = cb * 128 + warp_n * 32 + (lane & 3) * 2;
    #pragma unroll
    for (int nt = 0; nt < 4; nt++) {
        int col = cbase + nt * 8;
        if (col >= COLS) continue;
        float2 bias = *(const float2*)(g_bias + col);
        #pragma unroll
        for (int mt = 0; mt < 4; mt++) {
            int r0 = rbase + mt * 16;
            float2 v0, v1;
            v0.x = c[mt][nt][0] + bias.x; v0.y = c[mt][nt][1] + bias.y;
            v1.x = c[mt][nt][2] + bias.x; v1.y = c[mt][nt][3] + bias.y;
            *(float2*)(g_C + (size_t)r0 * COLS + col)       = v0;
            *(float2*)(g_C + (size_t)(r0 + 8) * COLS + col) = v1;
        }
    }
}

// ============================================================================
// Kernel 2: mixer. TWO warps per sample (agents split 8/8), log2-domain elu.
// ============================================================================
__global__ void __launch_bounds__(256)
mixer(const float* __restrict__ q_agents,
      const int*   __restrict__ actions,
      const float* __restrict__ W_v2,
      const float* __restrict__ b_v2,
      float*       __restrict__ out)
{
    const int gw = (blockIdx.x * blockDim.x + threadIdx.x) >> 5;
    if (gw >= NS * 2) return;
    const int n    = gw >> 1;
    const int half = gw & 1;
    const int lane = threadIdx.x & 31;
    const int eg   = lane >> 3;
    const int ms   = lane & 7;
    const int e0   = eg * 16;
    const unsigned FULL = 0xffffffffu;

    const float* Crow = g_C + (size_t)n * COLS;

    float qt_own = 0.f;
    if (lane < AG) {
        int a = actions[n * AG + lane];
        qt_own = q_agents[(size_t)(n * AG + lane) * ACT + a];
    }

    float zv0 = Crow[1152 + lane];
    float zv1 = Crow[1184 + lane];
    float vp  = fmaxf(zv0, 0.f) * W_v2[lane] + fmaxf(zv1, 0.f) * W_v2[lane + 32];
    #pragma unroll
    for (int off = 16; off >= 1; off >>= 1)
        vp += __shfl_xor_sync(FULL, vp, off);
    const float v = vp + b_v2[0];

    float u2[16];
    {
        const float4* p = (const float4*)(Crow + 1024 + e0);
        #pragma unroll
        for (int j = 0; j < 4; j++) {
            float4 t = p[j];
            u2[4 * j + 0] = t.x; u2[4 * j + 1] = t.y;
            u2[4 * j + 2] = t.z; u2[4 * j + 3] = t.w;
        }
    }
    #pragma unroll 1
    for (int i = 0; i < AG; i++) {
        float qti = __shfl_sync(FULL, qt_own, i);
        const float4* p = (const float4*)(Crow + i * EDIM + e0);
        #pragma unroll
        for (int j = 0; j < 4; j++) {
            float4 t = p[j];
            u2[4 * j + 0] = fmaf(qti, t.x, u2[4 * j + 0]);
            u2[4 * j + 1] = fmaf(qti, t.y, u2[4 * j + 1]);
            u2[4 * j + 2] = fmaf(qti, t.z, u2[4 * j + 2]);
            u2[4 * j + 3] = fmaf(qti, t.w, u2[4 * j + 3]);
        }
    }
    #pragma unroll
    for (int e = 0; e < 16; e++) u2[e] *= LOG2E;

    float wf[16], swf = 0.f;
    {
        const float4* p = (const float4*)(Crow + 1088 + e0);
        #pragma unroll
        for (int j = 0; j < 4; j++) {
            float4 t = p[j];
            wf[4 * j + 0] = t.x; wf[4 * j + 1] = t.y;
            wf[4 * j + 2] = t.z; wf[4 * j + 3] = t.w;
        }
        #pragma unroll
        for (int e = 0; e < 16; e++) swf += wf[e];
    }

    const int i0 = half * 8;
    #pragma unroll 1
    for (int i = i0; i < i0 + 8; i++) {
        float w[16];
        const float4* p = (const float4*)(Crow + i * EDIM + e0);
        #pragma unroll
        for (int j = 0; j < 4; j++) {
            float4 t = p[j];
            w[4 * j + 0] = t.x; w[4 * j + 1] = t.y;
            w[4 * j + 2] = t.z; w[4 * j + 3] = t.w;
        }
        float qti = __shfl_sync(FULL, qt_own, i);
        const float* qrow = q_agents + (size_t)(n * AG + i) * ACT;

        #pragma unroll
        for (int blk = 0; blk < 3; blk++) {
            int act  = blk * 8 + ms;
            int actc = act < (ACT - 1) ? act : (ACT - 1);
            float deltaL = (qrow[actc] - qti) * LOG2E;

            float acc1 = 0.f, acc2 = 0.f;
            #pragma unroll
            for (int e = 0; e < 16; e++) {
                float x2 = fmaf(deltaL, w[e], u2[e]);
                acc1 = fmaf(fmaxf(x2, 0.f), wf[e], acc1);
                acc2 = fmaf(ex2f(fminf(x2, 0.f)), wf[e], acc2);
            }
            float accv = fmaf(acc1, LN2, acc2) - swf;
            accv += __shfl_xor_sync(FULL, accv, 8);
            accv += __shfl_xor_sync(FULL, accv, 16);
            if (eg == 0 && act < ACT)
                out[(size_t)n * MOUT + i * ACT + act] = accv + v;
        }
    }
}

// ============================================================================
extern "C" void kernel_launch(void* const* d_in, const int* in_sizes, int n_in,
                              void* d_out, int out_size) {
    const float* q_agents = (const float*)d_in[0];
    const int*   actions  = (const int*)d_in[1];
    const float* state    = (const float*)d_in[2];
    const float* W_h1 = (const float*)d_in[3];
    const float* b_h1 = (const float*)d_in[4];
    const float* W_b1 = (const float*)d_in[5];
    const float* b_b1 = (const float*)d_in[6];
    const float* W_hf = (const float*)d_in[7];
    const float* b_hf = (const float*)d_in[8];
    const float* W_v1 = (const float*)d_in[9];
    const float* b_v1 = (const float*)d_in[10];
    const float* W_v2 = (const float*)d_in[11];
    const float* b_v2 = (const float*)d_in[12];
    float* out = (float*)d_out;

    cudaFuncSetAttribute(gemm_tc, cudaFuncAttributeMaxDynamicSharedMemorySize, GEMM_SMEM);

    int conv_threads = NS * SDIM / 4 + COLSP * SDIM / 4 + COLSP;
    convert_split<<<(conv_threads + 255) / 256, 256>>>(
        state, W_h1, b_h1, W_b1, b_b1, W_hf, b_hf, W_v1, b_v1);

    dim3 g1(10, 32);
    gemm_tc<<<g1, 256, GEMM_SMEM>>>();

    mixer<<<(NS * 2 * 32 + 255) / 256, 256>>>(q_agents, actions, W_v2, b_v2, out);
    (void)in_sizes; (void)n_in; (void)out_size;
}

// round 5
// speedup vs baseline: 2.3693x; 1.2613x over previous
#include <cuda_runtime.h>
#include <cuda_bf16.h>
#include <cuda_fp16.h>
#include <cstdint>

// ---------------- problem constants ----------------
#define NS    4096      // B*T
#define SDIM  512
#define AG    16
#define ACT   20
#define MOUT  320
#define EDIM  64
#define COLS  1216      // 1024 w1 + 64 b1 + 64 wf + 64 zv
#define COLSP 1280      // padded to 10*128

#define LOG2E 1.4426950408889634f
#define LN2   0.6931471805599453f

// ---------------- device scratch ----------------
__device__ float   g_C[NS * COLS];
__device__ __half  g_A0[NS * SDIM];          // fp16(state)
__device__ __half  g_B0[COLSP * SDIM];       // fp16(W)
__device__ float   g_bias[COLSP];

// ---------------- PTX helpers (sm_100-safe) ----------------
__device__ __forceinline__ uint32_t smem_u32(const void* p) {
    uint32_t a;
    asm("{ .reg .u64 t; cvta.to.shared.u64 t, %1; cvt.u32.u64 %0, t; }" : "=r"(a) : "l"(p));
    return a;
}
__device__ __forceinline__ void cp16(uint32_t dst, const void* src) {
    asm volatile("cp.async.cg.shared.global [%0], [%1], 16;" :: "r"(dst), "l"(src));
}
#define CP_COMMIT() asm volatile("cp.async.commit_group;" ::: "memory")
#define CP_WAIT3()  asm volatile("cp.async.wait_group 3;" ::: "memory")

__device__ __forceinline__ void ldm_x4(uint32_t* r, uint32_t addr) {
    asm volatile("ldmatrix.sync.aligned.m8n8.x4.shared.b16 {%0,%1,%2,%3}, [%4];"
        : "=r"(r[0]), "=r"(r[1]), "=r"(r[2]), "=r"(r[3]) : "r"(addr));
}
__device__ __forceinline__ void mma_f16(float* c, const uint32_t* a, uint32_t b0, uint32_t b1) {
    asm volatile(
        "mma.sync.aligned.m16n8k16.row.col.f32.f16.f16.f32 "
        "{%0,%1,%2,%3}, {%4,%5,%6,%7}, {%8,%9}, {%0,%1,%2,%3};"
        : "+f"(c[0]), "+f"(c[1]), "+f"(c[2]), "+f"(c[3])
        : "r"(a[0]), "r"(a[1]), "r"(a[2]), "r"(a[3]), "r"(b0), "r"(b1));
}
__device__ __forceinline__ float ex2f(float x) {
    float y;
    asm("ex2.approx.ftz.f32 %0, %1;" : "=f"(y) : "f"(x));
    return y;
}

// ============================================================================
// Kernel 0: A -> fp16; W -> fp16; concat bias.
// ============================================================================
__device__ __forceinline__ uint32_t pack2h(float a, float b) {
    __half2 t(__float2half_rn(a), __float2half_rn(b));
    return *(uint32_t*)&t;
}

__global__ void __launch_bounds__(256)
convert_split(const float* __restrict__ state,
              const float* __restrict__ W_h1, const float* __restrict__ b_h1,
              const float* __restrict__ W_b1, const float* __restrict__ b_b1,
              const float* __restrict__ W_hf, const float* __restrict__ b_hf,
              const float* __restrict__ W_v1, const float* __restrict__ b_v1)
{
    const int AQ = NS * SDIM / 4;        // 524288
    const int BQ = COLSP * SDIM / 4;     // 163840
    int idx = blockIdx.x * blockDim.x + threadIdx.x;

    if (idx < AQ) {
        float4 v = ((const float4*)state)[idx];
        uint2 p0;
        p0.x = pack2h(v.x, v.y);  p0.y = pack2h(v.z, v.w);
        ((uint2*)g_A0)[idx] = p0;
    } else if (idx < AQ + BQ) {
        int q = idx - AQ;
        int row = q >> 7;                // SDIM/4 = 128 quads per row
        int cq  = q & 127;
        float4 v = make_float4(0.f, 0.f, 0.f, 0.f);
        if (row < 1024)      v = ((const float4*)(W_h1 + (size_t)row * SDIM))[cq];
        else if (row < 1088) v = ((const float4*)(W_b1 + (size_t)(row - 1024) * SDIM))[cq];
        else if (row < 1152) v = ((const float4*)(W_hf + (size_t)(row - 1088) * SDIM))[cq];
        else if (row < 1216) v = ((const float4*)(W_v1 + (size_t)(row - 1152) * SDIM))[cq];
        uint2 p0;
        p0.x = pack2h(v.x, v.y);  p0.y = pack2h(v.z, v.w);
        ((uint2*)g_B0)[q] = p0;
    } else if (idx < AQ + BQ + COLSP) {
        int c = idx - AQ - BQ;
        float b = 0.f;
        if (c < 1024)      b = b_h1[c];
        else if (c < 1088) b = b_b1[c - 1024];
        else if (c < 1152) b = b_hf[c - 1088];
        else if (c < 1216) b = b_v1[c - 1152];
        g_bias[c] = b;
    }
}

// ============================================================================
// Kernel 1: HMMA fp16 GEMM, single term: C = A0*B0 + bias
// Tile 128(M) x 128(N) x 32(K). 256 threads = 8 warps (2m x 4n), warp 64x32.
// 4-stage cp.async pipeline, 2 CTAs/SM. 80B-padded rows -> conflict-free ldmatrix.
// ============================================================================
#define ROWB   80
#define MATB   (128 * ROWB)             // 10240 B
#define STAGEB (2 * MATB)               // 20480 B (A0,B0)
#define NSTAGE 4
#define GEMM_SMEM (NSTAGE * STAGEB)     // 81920 B

__device__ __forceinline__ void load_stage(uint32_t sb, int tid, int rowA, int rowB, int kt) {
    #pragma unroll
    for (int t = 0; t < 2; t++) {
        int id = tid + t * 256;          // 0..511
        int r  = id >> 2;                // 0..127
        int c  = id & 3;
        uint32_t soff = (uint32_t)(r * ROWB + c * 16);
        size_t gA = ((size_t)(rowA + r) * SDIM + kt) * 2 + c * 16;
        size_t gB = ((size_t)(rowB + r) * SDIM + kt) * 2 + c * 16;
        cp16(sb + 0 * MATB + soff, (const char*)g_A0 + gA);
        cp16(sb + 1 * MATB + soff, (const char*)g_B0 + gB);
    }
}

__global__ void __launch_bounds__(256, 2)
gemm_tc()
{
    extern __shared__ char smem[];
    const uint32_t sbase = smem_u32(smem);
    const int tid  = threadIdx.x;
    const int wid  = tid >> 5;
    const int lane = tid & 31;
    const int cb   = blockIdx.x;   // 0..9
    const int rb   = blockIdx.y;   // 0..31

    const int warp_m = wid >> 2;           // 0..1 -> m *64
    const int warp_n = wid & 3;            // 0..3 -> n *32
    const int rowA = rb * 128;
    const int rowB = cb * 128;

    float c[4][4][4];
    #pragma unroll
    for (int i = 0; i < 4; i++)
        #pragma unroll
        for (int j = 0; j < 4; j++)
            #pragma unroll
            for (int q = 0; q < 4; q++)
                c[i][j][q] = 0.f;

    load_stage(sbase + 0 * STAGEB, tid, rowA, rowB, 0);
    CP_COMMIT();
    load_stage(sbase + 1 * STAGEB, tid, rowA, rowB, 32);
    CP_COMMIT();
    load_stage(sbase + 2 * STAGEB, tid, rowA, rowB, 64);
    CP_COMMIT();

    const uint32_t lrow = (uint32_t)(lane & 15) * ROWB;
    const uint32_t lcol = (uint32_t)(lane >> 4) * 16;

    const int NK = SDIM / 32;   // 16
    for (int kt = 0; kt < NK; kt++) {
        if (kt + 3 < NK)
            load_stage(sbase + ((kt + 3) % NSTAGE) * STAGEB, tid, rowA, rowB, (kt + 3) * 32);
        CP_COMMIT();
        CP_WAIT3();
        __syncthreads();

        const uint32_t st = sbase + (kt % NSTAGE) * STAGEB;
        const uint32_t aAddr = st + lrow + lcol;
        const uint32_t bAddr = st + 1 * MATB + (uint32_t)(warp_n * 32) * ROWB + lrow + lcol;

        #pragma unroll
        for (int kk = 0; kk < 2; kk++) {
            uint32_t a[4][4];
            #pragma unroll
            for (int mt = 0; mt < 4; mt++) {
                uint32_t ra = aAddr + (uint32_t)((warp_m * 64 + mt * 16) * ROWB + kk * 32);
                ldm_x4(a[mt], ra);
            }
            uint32_t b0[2][4];
            #pragma unroll
            for (int nt2 = 0; nt2 < 2; nt2++) {
                uint32_t rbad = bAddr + (uint32_t)(nt2 * 16 * ROWB + kk * 32);
                ldm_x4(b0[nt2], rbad);
            }
            #pragma unroll
            for (int mt = 0; mt < 4; mt++) {
                #pragma unroll
                for (int nt = 0; nt < 4; nt++) {
                    int h = nt >> 1, o = nt & 1;
                    mma_f16(c[mt][nt], a[mt], b0[h][o], b0[h][o + 2]);
                }
            }
        }
        __syncthreads();
    }

    // epilogue
    const int rbase = rb * 128 + warp_m * 64 + (lane >> 2);
    const int cbase = cb * 128 + warp_n * 32 + (lane & 3) * 2;
    #pragma unroll
    for (int nt = 0; nt < 4; nt++) {
        int col = cbase + nt * 8;
        if (col >= COLS) continue;
        float2 bias = *(const float2*)(g_bias + col);
        #pragma unroll
        for (int mt = 0; mt < 4; mt++) {
            int r0 = rbase + mt * 16;
            float2 v0, v1;
            v0.x = c[mt][nt][0] + bias.x; v0.y = c[mt][nt][1] + bias.y;
            v1.x = c[mt][nt][2] + bias.x; v1.y = c[mt][nt][3] + bias.y;
            *(float2*)(g_C + (size_t)r0 * COLS + col)       = v0;
            *(float2*)(g_C + (size_t)(r0 + 8) * COLS + col) = v1;
        }
    }
}

// ============================================================================
// Kernel 2: mixer. TWO warps per sample (agents split 8/8), log2-domain elu.
// ============================================================================
__global__ void __launch_bounds__(256)
mixer(const float* __restrict__ q_agents,
      const int*   __restrict__ actions,
      const float* __restrict__ W_v2,
      const float* __restrict__ b_v2,
      float*       __restrict__ out)
{
    const int gw = (blockIdx.x * blockDim.x + threadIdx.x) >> 5;
    if (gw >= NS * 2) return;
    const int n    = gw >> 1;
    const int half = gw & 1;
    const int lane = threadIdx.x & 31;
    const int eg   = lane >> 3;
    const int ms   = lane & 7;
    const int e0   = eg * 16;
    const unsigned FULL = 0xffffffffu;

    const float* Crow = g_C + (size_t)n * COLS;

    float qt_own = 0.f;
    if (lane < AG) {
        int a = actions[n * AG + lane];
        qt_own = q_agents[(size_t)(n * AG + lane) * ACT + a];
    }

    float zv0 = Crow[1152 + lane];
    float zv1 = Crow[1184 + lane];
    float vp  = fmaxf(zv0, 0.f) * W_v2[lane] + fmaxf(zv1, 0.f) * W_v2[lane + 32];
    #pragma unroll
    for (int off = 16; off >= 1; off >>= 1)
        vp += __shfl_xor_sync(FULL, vp, off);
    const float v = vp + b_v2[0];

    float u2[16];
    {
        const float4* p = (const float4*)(Crow + 1024 + e0);
        #pragma unroll
        for (int j = 0; j < 4; j++) {
            float4 t = p[j];
            u2[4 * j + 0] = t.x; u2[4 * j + 1] = t.y;
            u2[4 * j + 2] = t.z; u2[4 * j + 3] = t.w;
        }
    }
    #pragma unroll 1
    for (int i = 0; i < AG; i++) {
        float qti = __shfl_sync(FULL, qt_own, i);
        const float4* p = (const float4*)(Crow + i * EDIM + e0);
        #pragma unroll
        for (int j = 0; j < 4; j++) {
            float4 t = p[j];
            u2[4 * j + 0] = fmaf(qti, t.x, u2[4 * j + 0]);
            u2[4 * j + 1] = fmaf(qti, t.y, u2[4 * j + 1]);
            u2[4 * j + 2] = fmaf(qti, t.z, u2[4 * j + 2]);
            u2[4 * j + 3] = fmaf(qti, t.w, u2[4 * j + 3]);
        }
    }
    #pragma unroll
    for (int e = 0; e < 16; e++) u2[e] *= LOG2E;

    float wf[16], swf = 0.f;
    {
        const float4* p = (const float4*)(Crow + 1088 + e0);
        #pragma unroll
        for (int j = 0; j < 4; j++) {
            float4 t = p[j];
            wf[4 * j + 0] = t.x; wf[4 * j + 1] = t.y;
            wf[4 * j + 2] = t.z; wf[4 * j + 3] = t.w;
        }
        #pragma unroll
        for (int e = 0; e < 16; e++) swf += wf[e];
    }

    const int i0 = half * 8;
    #pragma unroll 1
    for (int i = i0; i < i0 + 8; i++) {
        float w[16];
        const float4* p = (const float4*)(Crow + i * EDIM + e0);
        #pragma unroll
        for (int j = 0; j < 4; j++) {
            float4 t = p[j];
            w[4 * j + 0] = t.x; w[4 * j + 1] = t.y;
            w[4 * j + 2] = t.z; w[4 * j + 3] = t.w;
        }
        float qti = __shfl_sync(FULL, qt_own, i);
        const float* qrow = q_agents + (size_t)(n * AG + i) * ACT;

        #pragma unroll
        for (int blk = 0; blk < 3; blk++) {
            int act  = blk * 8 + ms;
            int actc = act < (ACT - 1) ? act : (ACT - 1);
            float deltaL = (qrow[actc] - qti) * LOG2E;

            float acc1 = 0.f, acc2 = 0.f;
            #pragma unroll
            for (int e = 0; e < 16; e++) {
                float x2 = fmaf(deltaL, w[e], u2[e]);
                acc1 = fmaf(fmaxf(x2, 0.f), wf[e], acc1);
                acc2 = fmaf(ex2f(fminf(x2, 0.f)), wf[e], acc2);
            }
            float accv = fmaf(acc1, LN2, acc2) - swf;
            accv += __shfl_xor_sync(FULL, accv, 8);
            accv += __shfl_xor_sync(FULL, accv, 16);
            if (eg == 0 && act < ACT)
                out[(size_t)n * MOUT + i * ACT + act] = accv + v;
        }
    }
}

// ============================================================================
extern "C" void kernel_launch(void* const* d_in, const int* in_sizes, int n_in,
                              void* d_out, int out_size) {
    const float* q_agents = (const float*)d_in[0];
    const int*   actions  = (const int*)d_in[1];
    const float* state    = (const float*)d_in[2];
    const float* W_h1 = (const float*)d_in[3];
    const float* b_h1 = (const float*)d_in[4];
    const float* W_b1 = (const float*)d_in[5];
    const float* b_b1 = (const float*)d_in[6];
    const float* W_hf = (const float*)d_in[7];
    const float* b_hf = (const float*)d_in[8];
    const float* W_v1 = (const float*)d_in[9];
    const float* b_v1 = (const float*)d_in[10];
    const float* W_v2 = (const float*)d_in[11];
    const float* b_v2 = (const float*)d_in[12];
    float* out = (float*)d_out;

    cudaFuncSetAttribute(gemm_tc, cudaFuncAttributeMaxDynamicSharedMemorySize, GEMM_SMEM);

    int conv_threads = NS * SDIM / 4 + COLSP * SDIM / 4 + COLSP;
    convert_split<<<(conv_threads + 255) / 256, 256>>>(
        state, W_h1, b_h1, W_b1, b_b1, W_hf, b_hf, W_v1, b_v1);

    dim3 g1(10, 32);
    gemm_tc<<<g1, 256, GEMM_SMEM>>>();

    mixer<<<(NS * 2 * 32 + 255) / 256, 256>>>(q_agents, actions, W_v2, b_v2, out);
    (void)in_sizes; (void)n_in; (void)out_size;
}

// round 6
// speedup vs baseline: 2.6495x; 1.1182x over previous
#include <cuda_runtime.h>
#include <cuda_bf16.h>
#include <cuda_fp16.h>
#include <cstdint>

// ---------------- problem constants ----------------
#define NS    4096      // B*T
#define SDIM  512
#define AG    16
#define ACT   20
#define MOUT  320
#define EDIM  64
#define COLS  1216      // 1024 w1 + 64 b1 + 64 wf + 64 zv
#define COLSP 1280      // padded to 8*160

#define LOG2E 1.4426950408889634f
#define LN2   0.6931471805599453f

// ---------------- device scratch ----------------
__device__ float   g_C[NS * COLS];
__device__ __half  g_A0[NS * SDIM];          // fp16(state)
__device__ __half  g_B0[COLSP * SDIM];       // fp16(W)
__device__ float   g_bias[COLSP];

// ---------------- PTX helpers (sm_100-safe) ----------------
__device__ __forceinline__ uint32_t smem_u32(const void* p) {
    uint32_t a;
    asm("{ .reg .u64 t; cvta.to.shared.u64 t, %1; cvt.u32.u64 %0, t; }" : "=r"(a) : "l"(p));
    return a;
}
__device__ __forceinline__ void cp16(uint32_t dst, const void* src) {
    asm volatile("cp.async.cg.shared.global [%0], [%1], 16;" :: "r"(dst), "l"(src));
}
#define CP_COMMIT() asm volatile("cp.async.commit_group;" ::: "memory")
#define CP_WAIT3()  asm volatile("cp.async.wait_group 3;" ::: "memory")

__device__ __forceinline__ void ldm_x4(uint32_t* r, uint32_t addr) {
    asm volatile("ldmatrix.sync.aligned.m8n8.x4.shared.b16 {%0,%1,%2,%3}, [%4];"
        : "=r"(r[0]), "=r"(r[1]), "=r"(r[2]), "=r"(r[3]) : "r"(addr));
}
__device__ __forceinline__ void ldm_x2(uint32_t* r, uint32_t addr) {
    asm volatile("ldmatrix.sync.aligned.m8n8.x2.shared.b16 {%0,%1}, [%2];"
        : "=r"(r[0]), "=r"(r[1]) : "r"(addr));
}
__device__ __forceinline__ void mma_f16(float* c, const uint32_t* a, uint32_t b0, uint32_t b1) {
    asm volatile(
        "mma.sync.aligned.m16n8k16.row.col.f32.f16.f16.f32 "
        "{%0,%1,%2,%3}, {%4,%5,%6,%7}, {%8,%9}, {%0,%1,%2,%3};"
        : "+f"(c[0]), "+f"(c[1]), "+f"(c[2]), "+f"(c[3])
        : "r"(a[0]), "r"(a[1]), "r"(a[2]), "r"(a[3]), "r"(b0), "r"(b1));
}

// ============================================================================
// Kernel 0: A -> fp16; W -> fp16; concat bias.
// ============================================================================
__device__ __forceinline__ uint32_t pack2h(float a, float b) {
    __half2 t(__float2half_rn(a), __float2half_rn(b));
    return *(uint32_t*)&t;
}

__global__ void __launch_bounds__(256)
convert_split(const float* __restrict__ state,
              const float* __restrict__ W_h1, const float* __restrict__ b_h1,
              const float* __restrict__ W_b1, const float* __restrict__ b_b1,
              const float* __restrict__ W_hf, const float* __restrict__ b_hf,
              const float* __restrict__ W_v1, const float* __restrict__ b_v1)
{
    const int AQ = NS * SDIM / 4;        // 524288
    const int BQ = COLSP * SDIM / 4;     // 163840
    int idx = blockIdx.x * blockDim.x + threadIdx.x;

    if (idx < AQ) {
        float4 v = ((const float4*)state)[idx];
        uint2 p0;
        p0.x = pack2h(v.x, v.y);  p0.y = pack2h(v.z, v.w);
        ((uint2*)g_A0)[idx] = p0;
    } else if (idx < AQ + BQ) {
        int q = idx - AQ;
        int row = q >> 7;                // SDIM/4 = 128 quads per row
        int cq  = q & 127;
        float4 v = make_float4(0.f, 0.f, 0.f, 0.f);
        if (row < 1024)      v = ((const float4*)(W_h1 + (size_t)row * SDIM))[cq];
        else if (row < 1088) v = ((const float4*)(W_b1 + (size_t)(row - 1024) * SDIM))[cq];
        else if (row < 1152) v = ((const float4*)(W_hf + (size_t)(row - 1088) * SDIM))[cq];
        else if (row < 1216) v = ((const float4*)(W_v1 + (size_t)(row - 1152) * SDIM))[cq];
        uint2 p0;
        p0.x = pack2h(v.x, v.y);  p0.y = pack2h(v.z, v.w);
        ((uint2*)g_B0)[q] = p0;
    } else if (idx < AQ + BQ + COLSP) {
        int c = idx - AQ - BQ;
        float b = 0.f;
        if (c < 1024)      b = b_h1[c];
        else if (c < 1088) b = b_b1[c - 1024];
        else if (c < 1152) b = b_hf[c - 1088];
        else if (c < 1216) b = b_v1[c - 1152];
        g_bias[c] = b;
    }
}

// ============================================================================
// Kernel 1: HMMA fp16 GEMM: C = A0*B0 + bias
// Tile 128(M) x 160(N) x 32(K). grid (8, 32) = 256 CTAs -> single 2/SM wave.
// 256 threads = 8 warps (2m x 4n), warp tile 64x40 (5 n-frags).
// 4-stage cp.async pipeline. 80B-padded rows -> conflict-free ldmatrix.
// ============================================================================
#define ROWB   80
#define MATBA  (128 * ROWB)             // 10240 B (A: 128 rows)
#define MATBB  (160 * ROWB)             // 12800 B (B: 160 rows)
#define STAGEB (MATBA + MATBB)          // 23040 B
#define NSTAGE 4
#define GEMM_SMEM (NSTAGE * STAGEB)     // 92160 B
#define NCHUNKS ((128 + 160) * 4)       // 1152 16B-chunks per stage

__device__ __forceinline__ void load_stage(uint32_t sb, int tid, int rowA, int rowB, int kt) {
    #pragma unroll
    for (int t = 0; t < 5; t++) {
        int id = tid + t * 256;          // 0..1279
        if (id < NCHUNKS) {
            if (id < 512) {
                int r = id >> 2, c = id & 3;
                cp16(sb + (uint32_t)(r * ROWB + c * 16),
                     (const char*)g_A0 + ((size_t)(rowA + r) * SDIM + kt) * 2 + c * 16);
            } else {
                int q = id - 512;
                int r = q >> 2, c = q & 3;
                cp16(sb + MATBA + (uint32_t)(r * ROWB + c * 16),
                     (const char*)g_B0 + ((size_t)(rowB + r) * SDIM + kt) * 2 + c * 16);
            }
        }
    }
}

__global__ void __launch_bounds__(256, 2)
gemm_tc()
{
    extern __shared__ char smem[];
    const uint32_t sbase = smem_u32(smem);
    const int tid  = threadIdx.x;
    const int wid  = tid >> 5;
    const int lane = tid & 31;
    const int cb   = blockIdx.x;   // 0..7  (160-col blocks)
    const int rb   = blockIdx.y;   // 0..31 (128-row blocks)

    const int warp_m = wid >> 2;           // 0..1 -> m *64
    const int warp_n = wid & 3;            // 0..3 -> n *40
    const int rowA = rb * 128;
    const int rowB = cb * 160;

    float c[4][5][4];
    #pragma unroll
    for (int i = 0; i < 4; i++)
        #pragma unroll
        for (int j = 0; j < 5; j++)
            #pragma unroll
            for (int q = 0; q < 4; q++)
                c[i][j][q] = 0.f;

    load_stage(sbase + 0 * STAGEB, tid, rowA, rowB, 0);
    CP_COMMIT();
    load_stage(sbase + 1 * STAGEB, tid, rowA, rowB, 32);
    CP_COMMIT();
    load_stage(sbase + 2 * STAGEB, tid, rowA, rowB, 64);
    CP_COMMIT();

    // ldmatrix per-lane addressing
    const uint32_t lrow  = (uint32_t)(lane & 15) * ROWB;       // x4: 16 rows
    const uint32_t lcol  = (uint32_t)(lane >> 4) * 16;         // x4: 2 k-halves
    const uint32_t lrow2 = (uint32_t)(lane & 7) * ROWB;        // x2: 8 rows
    const uint32_t lcol2 = (uint32_t)((lane >> 3) & 1) * 16;   // x2: 2 k-halves

    const int NK = SDIM / 32;   // 16
    for (int kt = 0; kt < NK; kt++) {
        if (kt + 3 < NK)
            load_stage(sbase + ((kt + 3) % NSTAGE) * STAGEB, tid, rowA, rowB, (kt + 3) * 32);
        CP_COMMIT();
        CP_WAIT3();
        __syncthreads();

        const uint32_t st = sbase + (kt % NSTAGE) * STAGEB;
        const uint32_t aAddr   = st + lrow + lcol;
        const uint32_t bBase   = st + MATBA + (uint32_t)(warp_n * 40) * ROWB;
        const uint32_t bAddrX4 = bBase + lrow + lcol;
        const uint32_t bAddrX2 = bBase + 32 * ROWB + lrow2 + lcol2;

        #pragma unroll
        for (int kk = 0; kk < 2; kk++) {
            uint32_t a[4][4];
            #pragma unroll
            for (int mt = 0; mt < 4; mt++)
                ldm_x4(a[mt], aAddr + (uint32_t)((warp_m * 64 + mt * 16) * ROWB + kk * 32));

            uint32_t b4a[4], b4b[4], b2[2];
            ldm_x4(b4a, bAddrX4 + (uint32_t)(kk * 32));
            ldm_x4(b4b, bAddrX4 + (uint32_t)(16 * ROWB + kk * 32));
            ldm_x2(b2,  bAddrX2 + (uint32_t)(kk * 32));

            #pragma unroll
            for (int mt = 0; mt < 4; mt++) {
                mma_f16(c[mt][0], a[mt], b4a[0], b4a[2]);
                mma_f16(c[mt][1], a[mt], b4a[1], b4a[3]);
                mma_f16(c[mt][2], a[mt], b4b[0], b4b[2]);
                mma_f16(c[mt][3], a[mt], b4b[1], b4b[3]);
                mma_f16(c[mt][4], a[mt], b2[0],  b2[1]);
            }
        }
        __syncthreads();
    }

    // epilogue
    const int rbase = rb * 128 + warp_m * 64 + (lane >> 2);
    const int cbase = cb * 160 + warp_n * 40 + (lane & 3) * 2;
    #pragma unroll
    for (int nt = 0; nt < 5; nt++) {
        int col = cbase + nt * 8;
        if (col >= COLS) continue;
        float2 bias = *(const float2*)(g_bias + col);
        #pragma unroll
        for (int mt = 0; mt < 4; mt++) {
            int r0 = rbase + mt * 16;
            float2 v0, v1;
            v0.x = c[mt][nt][0] + bias.x; v0.y = c[mt][nt][1] + bias.y;
            v1.x = c[mt][nt][2] + bias.x; v1.y = c[mt][nt][3] + bias.y;
            *(float2*)(g_C + (size_t)r0 * COLS + col)       = v0;
            *(float2*)(g_C + (size_t)(r0 + 8) * COLS + col) = v1;
        }
    }
}

// ============================================================================
// Kernel 2: mixer v3. TWO warps per sample (agents split 8/8).
// Lane = eg*4 + slot: 8 e-groups of 8 e-values x 4 action slots; 5 rounds
// cover all 20 actions exactly (no clamp waste). Exponentials paired through
// ex2.approx.f16x2 (h2exp2): one MUFU op per 2 evals; args/accums stay fp32.
// ============================================================================
__global__ void __launch_bounds__(256)
mixer(const float* __restrict__ q_agents,
      const int*   __restrict__ actions,
      const float* __restrict__ W_v2,
      const float* __restrict__ b_v2,
      float*       __restrict__ out)
{
    const int gw = (blockIdx.x * blockDim.x + threadIdx.x) >> 5;
    if (gw >= NS * 2) return;
    const int n    = gw >> 1;
    const int half = gw & 1;
    const int lane = threadIdx.x & 31;
    const int eg   = lane >> 2;         // 0..7 -> 8 e-values each
    const int slot = lane & 3;          // 0..3 action slot
    const int e0   = eg * 8;
    const unsigned FULL = 0xffffffffu;

    const float* Crow = g_C + (size_t)n * COLS;

    float qt_own = 0.f;
    if (lane < AG) {
        int a = actions[n * AG + lane];
        qt_own = q_agents[(size_t)(n * AG + lane) * ACT + a];
    }

    // v = relu(zv) @ W_v2 + b_v2 (full-warp over 64 cols)
    float zv0 = Crow[1152 + lane];
    float zv1 = Crow[1184 + lane];
    float vp  = fmaxf(zv0, 0.f) * W_v2[lane] + fmaxf(zv1, 0.f) * W_v2[lane + 32];
    #pragma unroll
    for (int off = 16; off >= 1; off >>= 1)
        vp += __shfl_xor_sync(FULL, vp, off);
    const float v = vp + b_v2[0];

    // u2[e] = LOG2E * (b1[e] + sum_j qt[j]*w1[j,e]) over this lane's 8-e slice
    float u2[8];
    {
        float4 t0 = *(const float4*)(Crow + 1024 + e0);
        float4 t1 = *(const float4*)(Crow + 1024 + e0 + 4);
        u2[0]=t0.x; u2[1]=t0.y; u2[2]=t0.z; u2[3]=t0.w;
        u2[4]=t1.x; u2[5]=t1.y; u2[6]=t1.z; u2[7]=t1.w;
    }
    #pragma unroll 1
    for (int i = 0; i < AG; i++) {
        float qti = __shfl_sync(FULL, qt_own, i);
        float4 t0 = *(const float4*)(Crow + i * EDIM + e0);
        float4 t1 = *(const float4*)(Crow + i * EDIM + e0 + 4);
        u2[0] = fmaf(qti, t0.x, u2[0]); u2[1] = fmaf(qti, t0.y, u2[1]);
        u2[2] = fmaf(qti, t0.z, u2[2]); u2[3] = fmaf(qti, t0.w, u2[3]);
        u2[4] = fmaf(qti, t1.x, u2[4]); u2[5] = fmaf(qti, t1.y, u2[5]);
        u2[6] = fmaf(qti, t1.z, u2[6]); u2[7] = fmaf(qti, t1.w, u2[7]);
    }
    #pragma unroll
    for (int e = 0; e < 8; e++) u2[e] *= LOG2E;

    // wf slice + lane-partial sum (folds the elu "-1")
    float wf[8], swf = 0.f;
    {
        float4 t0 = *(const float4*)(Crow + 1088 + e0);
        float4 t1 = *(const float4*)(Crow + 1088 + e0 + 4);
        wf[0]=t0.x; wf[1]=t0.y; wf[2]=t0.z; wf[3]=t0.w;
        wf[4]=t1.x; wf[5]=t1.y; wf[6]=t1.z; wf[7]=t1.w;
        #pragma unroll
        for (int e = 0; e < 8; e++) swf += wf[e];
    }

    const int i0 = half * 8;
    #pragma unroll 1
    for (int i = i0; i < i0 + 8; i++) {
        float w[8];
        {
            float4 t0 = *(const float4*)(Crow + i * EDIM + e0);
            float4 t1 = *(const float4*)(Crow + i * EDIM + e0 + 4);
            w[0]=t0.x; w[1]=t0.y; w[2]=t0.z; w[3]=t0.w;
            w[4]=t1.x; w[5]=t1.y; w[6]=t1.z; w[7]=t1.w;
        }
        float qti = __shfl_sync(FULL, qt_own, i);
        const float* qrow = q_agents + (size_t)(n * AG + i) * ACT;

        #pragma unroll
        for (int r = 0; r < 5; r++) {
            int act = r * 4 + slot;                       // 0..19 exactly
            float deltaL = (qrow[act] - qti) * LOG2E;

            float acc1 = 0.f, acc2 = 0.f;
            #pragma unroll
            for (int p = 0; p < 4; p++) {
                float xa = fmaf(deltaL, w[2*p],   u2[2*p]);
                float xb = fmaf(deltaL, w[2*p+1], u2[2*p+1]);
                acc1 = fmaf(fmaxf(xa, 0.f), wf[2*p],   acc1);
                acc1 = fmaf(fmaxf(xb, 0.f), wf[2*p+1], acc1);
                __half2 h = __floats2half2_rn(fminf(xa, 0.f), fminf(xb, 0.f));
                __half2 t = h2exp2(h);
                acc2 = fmaf(__low2float(t),  wf[2*p],   acc2);
                acc2 = fmaf(__high2float(t), wf[2*p+1], acc2);
            }
            float accv = fmaf(acc1, LN2, acc2) - swf;
            accv += __shfl_xor_sync(FULL, accv, 4);
            accv += __shfl_xor_sync(FULL, accv, 8);
            accv += __shfl_xor_sync(FULL, accv, 16);
            if (eg == 0)
                out[(size_t)n * MOUT + i * ACT + act] = accv + v;
        }
    }
}

// ============================================================================
extern "C" void kernel_launch(void* const* d_in, const int* in_sizes, int n_in,
                              void* d_out, int out_size) {
    const float* q_agents = (const float*)d_in[0];
    const int*   actions  = (const int*)d_in[1];
    const float* state    = (const float*)d_in[2];
    const float* W_h1 = (const float*)d_in[3];
    const float* b_h1 = (const float*)d_in[4];
    const float* W_b1 = (const float*)d_in[5];
    const float* b_b1 = (const float*)d_in[6];
    const float* W_hf = (const float*)d_in[7];
    const float* b_hf = (const float*)d_in[8];
    const float* W_v1 = (const float*)d_in[9];
    const float* b_v1 = (const float*)d_in[10];
    const float* W_v2 = (const float*)d_in[11];
    const float* b_v2 = (const float*)d_in[12];
    float* out = (float*)d_out;

    cudaFuncSetAttribute(gemm_tc, cudaFuncAttributeMaxDynamicSharedMemorySize, GEMM_SMEM);

    int conv_threads = NS * SDIM / 4 + COLSP * SDIM / 4 + COLSP;
    convert_split<<<(conv_threads + 255) / 256, 256>>>(
        state, W_h1, b_h1, W_b1, b_b1, W_hf, b_hf, W_v1, b_v1);

    dim3 g1(8, 32);
    gemm_tc<<<g1, 256, GEMM_SMEM>>>();

    mixer<<<(NS * 2 * 32 + 255) / 256, 256>>>(q_agents, actions, W_v2, b_v2, out);
    (void)in_sizes; (void)n_in; (void)out_size;
}